// round 15
// baseline (speedup 1.0000x reference)
#include <cuda_runtime.h>
#include <cuda_fp16.h>
#include <math.h>

// Problem constants
#define BB     2
#define HEADS  8
#define LEVELS 3
#define POINTS 4
#define CC     256
#define HD     32          // CC / HEADS
#define NV     5376        // 64*64 + 32*32 + 16*16
#define NQ     5376
#define TP     96          // HEADS*LEVELS*POINTS
#define TP2    192
#define NBQH   (BB * NQ * HEADS)   // 86016

// Padded value-tensor geometry: each level padded by a 1-cell zero ring.
// L0: 66x66 = 4356, L1: 34x34 = 1156, L2: 18x18 = 324.  Total 5836 cells/batch.
#define PNV    5836
#define P0     0
#define P1     4356
#define P2     5512
#define VP_TOTAL  (BB * PNV * CC)      // 2,988,032 elements
#define NBORDER   460                  // border cells per batch (260+132+68)

// Scratch (static device allocations — allowed by harness rules)
__device__ __half  g_vph[VP_TOTAL];        // padded value @ Wv^T + bv, fp16
__device__ float   g_off[BB * NQ * TP2];   // sampling offsets
__device__ float   g_a[BB * NQ * TP];      // attention logits
__device__ float4  g_w4[12 * NBQH];        // premult corner weights, [pp][bqh]
__device__ int     g_pidx[12 * NBQH];      // folded element-index of corner(0,0), [pp][bqh]

// ---------------------------------------------------------------------------
// Zero ONLY the border cells of the padded v buffer (interior is overwritten
// by the v-GEMM every call). 2*460 cells x 256ch -> 29440 uint4 stores, ~0.3us.
// Runs concurrently with the v-GEMM (disjoint cells).
// ---------------------------------------------------------------------------
__global__ void __launch_bounds__(256) zero_border_kernel()
{
    int i = blockIdx.x * blockDim.x + threadIdx.x;
    if (i >= BB * NBORDER * 32) return;
    int chunk = i & 31;          // 8-half chunk within the 256 channels
    int r = i >> 5;
    int b = r / NBORDER;
    int j = r % NBORDER;
    int Pw, pb, s;
    if (j < 260)      { Pw = 66; pb = P0; s = j; }
    else if (j < 392) { Pw = 34; pb = P1; s = j - 260; }
    else              { Pw = 18; pb = P2; s = j - 392; }
    int y, x;
    if (s < Pw)            { y = 0;      x = s; }
    else if (s < 2 * Pw)   { y = Pw - 1; x = s - Pw; }
    else {
        int t = s - 2 * Pw;
        if (t < Pw - 2) { y = 1 + t;            x = 0; }
        else            { y = 1 + t - (Pw - 2); x = Pw - 1; }
    }
    int pcell = pb + y * Pw + x;
    *(uint4*)&g_vph[((size_t)b * PNV + pcell) * CC + chunk * 8] = make_uint4(0u, 0u, 0u, 0u);
}

// ---------------------------------------------------------------------------
// Tensor-core GEMM (tf32 mma.sync) — R9/R11 winner, unchanged math.
// pad_v != 0: epilogue remaps rows into padded g_vph layout as fp16.
// ---------------------------------------------------------------------------
#define GBm 128
#define GBn 64
#define GBk 32
#define SSTR 36

__device__ __forceinline__ unsigned f2tf32(float f) {
    unsigned u;
    asm("cvt.rna.tf32.f32 %0, %1;" : "=r"(u) : "f"(f));
    return u;
}

__device__ __forceinline__ int padded_row(int gm) {
    int b = gm / NV;
    int n = gm - b * NV;
    int pbase, cell;
    if (n < 4096)      { int y = n >> 6, x = n & 63;                   pbase = P0; cell = (y + 1) * 66 + (x + 1); }
    else if (n < 5120) { int t = n - 4096; int y = t >> 5, x = t & 31; pbase = P1; cell = (y + 1) * 34 + (x + 1); }
    else               { int t = n - 5120; int y = t >> 4, x = t & 15; pbase = P2; cell = (y + 1) * 18 + (x + 1); }
    return b * PNV + pbase + cell;
}

__global__ void __launch_bounds__(256, 2) gemm_tf32_kernel(
    const float* __restrict__ A, const float* __restrict__ W,
    const float* __restrict__ bias, float* __restrict__ C,
    int M, int N, int K, int pad_v)
{
    __shared__ unsigned As[GBm][SSTR];
    __shared__ unsigned Ws[GBn][SSTR];

    const int tid  = threadIdx.x;
    const int lane = tid & 31;
    const int warp = tid >> 5;
    const int wm   = warp >> 1;
    const int wn   = warp & 1;
    const int m0   = blockIdx.y * GBm;
    const int n0   = blockIdx.x * GBn;

    const int grp = lane >> 2;
    const int tig = lane & 3;

    int ar[4], ac[4];
    size_t aoff[4];
#pragma unroll
    for (int j = 0; j < 4; j++) {
        int idx = tid + j * 256;
        ar[j] = idx >> 3;
        ac[j] = idx & 7;
        aoff[j] = (size_t)(m0 + ar[j]) * K + ac[j] * 4;
    }
    int wr[2], wc[2], wg[2];
    size_t woff[2];
#pragma unroll
    for (int j = 0; j < 2; j++) {
        int idx = tid + j * 256;
        wr[j] = idx >> 3;
        wc[j] = idx & 7;
        wg[j] = n0 + wr[j];
        woff[j] = (size_t)wg[j] * K + wc[j] * 4;
    }

    float c[2][4][4];
#pragma unroll
    for (int mt = 0; mt < 2; mt++)
#pragma unroll
        for (int nt = 0; nt < 4; nt++)
#pragma unroll
            for (int i = 0; i < 4; i++) c[mt][nt][i] = 0.f;

    float4 pa[4], pw[2];
#pragma unroll
    for (int j = 0; j < 4; j++) pa[j] = *(const float4*)&A[aoff[j]];
#pragma unroll
    for (int j = 0; j < 2; j++)
        pw[j] = (wg[j] < N) ? *(const float4*)&W[woff[j]]
                            : make_float4(0.f, 0.f, 0.f, 0.f);

    for (int k0 = 0; k0 < K; k0 += GBk) {
#pragma unroll
        for (int j = 0; j < 4; j++) {
            uint4 u;
            u.x = f2tf32(pa[j].x); u.y = f2tf32(pa[j].y);
            u.z = f2tf32(pa[j].z); u.w = f2tf32(pa[j].w);
            *(uint4*)&As[ar[j]][ac[j] * 4] = u;
        }
#pragma unroll
        for (int j = 0; j < 2; j++) {
            uint4 u;
            u.x = f2tf32(pw[j].x); u.y = f2tf32(pw[j].y);
            u.z = f2tf32(pw[j].z); u.w = f2tf32(pw[j].w);
            *(uint4*)&Ws[wr[j]][wc[j] * 4] = u;
        }
        __syncthreads();

        const int kn = k0 + GBk;
        if (kn < K) {
#pragma unroll
            for (int j = 0; j < 4; j++) pa[j] = *(const float4*)&A[aoff[j] + kn];
#pragma unroll
            for (int j = 0; j < 2; j++)
                pw[j] = (wg[j] < N) ? *(const float4*)&W[woff[j] + kn]
                                    : make_float4(0.f, 0.f, 0.f, 0.f);
        }

#pragma unroll
        for (int kk = 0; kk < GBk; kk += 8) {
            unsigned a[2][4];
#pragma unroll
            for (int mt = 0; mt < 2; mt++) {
                int rb = wm * 32 + mt * 16;
                a[mt][0] = As[rb + grp][kk + tig];
                a[mt][1] = As[rb + grp + 8][kk + tig];
                a[mt][2] = As[rb + grp][kk + tig + 4];
                a[mt][3] = As[rb + grp + 8][kk + tig + 4];
            }
            unsigned b[4][2];
#pragma unroll
            for (int nt = 0; nt < 4; nt++) {
                int cb = wn * 32 + nt * 8;
                b[nt][0] = Ws[cb + grp][kk + tig];
                b[nt][1] = Ws[cb + grp][kk + tig + 4];
            }
#pragma unroll
            for (int mt = 0; mt < 2; mt++)
#pragma unroll
                for (int nt = 0; nt < 4; nt++) {
                    asm volatile(
                        "mma.sync.aligned.m16n8k8.row.col.f32.tf32.tf32.f32 "
                        "{%0,%1,%2,%3}, {%4,%5,%6,%7}, {%8,%9}, {%0,%1,%2,%3};"
                        : "+f"(c[mt][nt][0]), "+f"(c[mt][nt][1]),
                          "+f"(c[mt][nt][2]), "+f"(c[mt][nt][3])
                        : "r"(a[mt][0]), "r"(a[mt][1]), "r"(a[mt][2]), "r"(a[mt][3]),
                          "r"(b[nt][0]), "r"(b[nt][1]));
                }
        }
        __syncthreads();
    }

    // ---- epilogue ----
    int row0[2], row1[2];
#pragma unroll
    for (int mt = 0; mt < 2; mt++) {
        int gm = m0 + wm * 32 + mt * 16 + grp;
        row0[mt] = pad_v ? padded_row(gm) : gm;
        row1[mt] = pad_v ? padded_row(gm + 8) : gm + 8;
    }
#pragma unroll
    for (int nt = 0; nt < 4; nt++) {
        int gn = n0 + wn * 32 + nt * 8 + tig * 2;
        if (gn >= N) continue;
        float b0 = bias[gn];
        float b1 = bias[gn + 1];
#pragma unroll
        for (int mt = 0; mt < 2; mt++) {
            float2 o0 = make_float2(c[mt][nt][0] + b0, c[mt][nt][1] + b1);
            float2 o1 = make_float2(c[mt][nt][2] + b0, c[mt][nt][3] + b1);
            if (pad_v) {
                *(__half2*)&g_vph[(size_t)row0[mt] * N + gn] = __floats2half2_rn(o0.x, o0.y);
                *(__half2*)&g_vph[(size_t)row1[mt] * N + gn] = __floats2half2_rn(o1.x, o1.y);
            } else {
                *(float2*)&C[(size_t)row0[mt] * N + gn] = o0;
                *(float2*)&C[(size_t)row1[mt] * N + gn] = o1;
            }
        }
    }
}

// ---------------------------------------------------------------------------
// Precompute: softmax + sampling coordinates/weights, once per (b,q,h).
// (unchanged from R14)
// ---------------------------------------------------------------------------
__global__ void __launch_bounds__(256) precompute_kernel(
    const float* __restrict__ refpts)
{
    const int t = blockIdx.x * blockDim.x + threadIdx.x;
    if (t >= NBQH) return;
    const int h  = t % HEADS;
    const int bq = t / HEADS;
    const int b  = bq / NQ;

    const float rx = refpts[bq * 2 + 0];
    const float ry = refpts[bq * 2 + 1];

    const float* __restrict__ off   = g_off + bq * TP2 + h * (LEVELS * POINTS * 2);
    const float* __restrict__ logit = g_a   + bq * TP  + h * (LEVELS * POINTS);

    float e[12];
    float mx = -INFINITY;
#pragma unroll
    for (int i = 0; i < 12; i++) { e[i] = logit[i]; mx = fmaxf(mx, e[i]); }
    float s = 0.f;
#pragma unroll
    for (int i = 0; i < 12; i++) { e[i] = __expf(e[i] - mx); s += e[i]; }
    const float inv = 1.f / s;

    const int plvl_start[LEVELS] = {P0, P1, P2};
    const int lvl_dim[LEVELS]    = {64, 32, 16};

#pragma unroll
    for (int lvl = 0; lvl < LEVELS; lvl++) {
        const int Wd = lvl_dim[lvl];
        const int Pw = Wd + 2;
        const int lbase = b * PNV + plvl_start[lvl];
        const float fW = (float)Wd;
#pragma unroll
        for (int p = 0; p < POINTS; p++) {
            const int pp = lvl * POINTS + p;
            float lx = rx + off[pp * 2 + 0];
            float ly = ry + off[pp * 2 + 1];
            lx = fminf(fmaxf(lx, 0.f), 1.f);
            ly = fminf(fmaxf(ly, 0.f), 1.f);
            const float aw = e[pp] * inv;

            const float x = lx * fW - 0.5f;
            const float y = ly * fW - 0.5f;   // Hd == Wd
            const float x0f = floorf(x);
            const float y0f = floorf(y);
            const int x0 = (int)x0f;
            const int y0 = (int)y0f;
            const float wx1 = x - x0f;
            const float wy1 = y - y0f;
            const float wx0 = 1.f - wx1;
            const float wy0 = 1.f - wy1;

            float4 w4;
            w4.x = aw * wx0 * wy0;
            w4.y = aw * wx1 * wy0;
            w4.z = aw * wx0 * wy1;
            w4.w = aw * wx1 * wy1;

            const int cell00 = (y0 + 1) * Pw + (x0 + 1);
            const int idx00  = (lbase + cell00) * CC + h * HD;

            g_w4 [pp * NBQH + t] = w4;
            g_pidx[pp * NBQH + t] = idx00;
        }
    }
}

// ---------------------------------------------------------------------------
// FUSED sampling + out-GEMM.
// Grid: 336 blocks x 256 thr; block owns MT=32 query rows (bq = blk*32..+32).
// Phase 1: warp w samples head w for all 32 rows (R14 fp16 gather body),
//          storing tf32-converted results into smem A-tile Atf[32][260].
// Phase 2: block computes out[32,256] = Atf @ Wo^T + bo via the proven
//          tf32 mma warp loop (warp w owns n-range w*32..+32).
// Tensor-phase of one CTA hides under the gather stalls of the co-resident CTA.
// ---------------------------------------------------------------------------
#define MT 32
#define ASTR (CC + 4)    // 260: odd*4 -> conflict-free fragment LDS

__global__ void __launch_bounds__(256, 2) fused_sample_out_kernel(
    const float* __restrict__ Wo, const float* __restrict__ bo,
    float* __restrict__ out)
{
    __shared__ unsigned Atf[MT][ASTR];    // sampled tile, tf32 bits, [m][k]
    __shared__ unsigned Wos[CC][SSTR];    // Wo k-tile, [n][k], stride 36

    const int tid  = threadIdx.x;
    const int lane = tid & 31;
    const int warp = tid >> 5;            // == head h in phase 1
    const int blk  = blockIdx.x;

    // ---------------- Phase 1: sampling ----------------
    {
        const int pt = (lane >> 4) & 1;   // point within pair
        const int cg = (lane >> 2) & 3;   // corner
        const int q  = lane & 3;          // 8-channel chunk
        const int dx = cg & 1;
        const int dy = cg >> 1;

        const int coff0 = (dy * 66 + dx) * CC + q * 8;
        const int coff1 = (dy * 34 + dx) * CC + q * 8;
        const int coff2 = (dy * 18 + dx) * CC + q * 8;

        for (int m = 0; m < MT; m++) {
            const int gidx = (blk * MT + m) * HEADS + warp;   // (b,q,h) task

            float acc[8];
#pragma unroll
            for (int j = 0; j < 8; j++) acc[j] = 0.f;

#pragma unroll
            for (int it = 0; it < 6; it++) {
                const int pp = 2 * it + pt;
                const float4 w4  = g_w4 [pp * NBQH + gidx];
                const int  idx00 = g_pidx[pp * NBQH + gidx];

                const float w = (cg == 0) ? w4.x : (cg == 1) ? w4.y
                              : (cg == 2) ? w4.z : w4.w;

                const int coff = (it < 2) ? coff0 : (it < 4) ? coff1 : coff2;
                const uint4 raw = *(const uint4*)&g_vph[idx00 + coff];
                const __half2* h2 = (const __half2*)&raw;
#pragma unroll
                for (int j = 0; j < 4; j++) {
                    const float2 f = __half22float2(h2[j]);
                    acc[2 * j + 0] = fmaf(w, f.x, acc[2 * j + 0]);
                    acc[2 * j + 1] = fmaf(w, f.y, acc[2 * j + 1]);
                }
            }

#pragma unroll
            for (int ofs = 4; ofs <= 16; ofs <<= 1) {
#pragma unroll
                for (int j = 0; j < 8; j++)
                    acc[j] += __shfl_xor_sync(0xffffffffu, acc[j], ofs);
            }

            if (lane < 4) {
                // lane holds chunk q == lane: channels warp*32 + lane*8 .. +8
                uint4 u0, u1;
                u0.x = f2tf32(acc[0]); u0.y = f2tf32(acc[1]);
                u0.z = f2tf32(acc[2]); u0.w = f2tf32(acc[3]);
                u1.x = f2tf32(acc[4]); u1.y = f2tf32(acc[5]);
                u1.z = f2tf32(acc[6]); u1.w = f2tf32(acc[7]);
                *(uint4*)&Atf[m][warp * HD + lane * 8]     = u0;
                *(uint4*)&Atf[m][warp * HD + lane * 8 + 4] = u1;
            }
        }
    }
    __syncthreads();

    // ---------------- Phase 2: out = Atf @ Wo^T + bo ----------------
    const int grp = lane >> 2;
    const int tig = lane & 3;

    float c[2][4][4];
#pragma unroll
    for (int mt = 0; mt < 2; mt++)
#pragma unroll
        for (int nt = 0; nt < 4; nt++)
#pragma unroll
            for (int i = 0; i < 4; i++) c[mt][nt][i] = 0.f;

    for (int k0 = 0; k0 < CC; k0 += GBk) {
        // load Wo tile: 256 n-rows x 32 k = 2048 float4, 8 per thread
#pragma unroll
        for (int j = 0; j < 8; j++) {
            int idx = tid + j * 256;
            int r = idx >> 3;            // n-row 0..255
            int cc4 = idx & 7;           // k-float4
            float4 f = *(const float4*)&Wo[(size_t)r * CC + k0 + cc4 * 4];
            uint4 u;
            u.x = f2tf32(f.x); u.y = f2tf32(f.y);
            u.z = f2tf32(f.z); u.w = f2tf32(f.w);
            *(uint4*)&Wos[r][cc4 * 4] = u;
        }
        __syncthreads();

#pragma unroll
        for (int kk = 0; kk < GBk; kk += 8) {
            unsigned a[2][4];
#pragma unroll
            for (int mt = 0; mt < 2; mt++) {
                int rb = mt * 16;
                a[mt][0] = Atf[rb + grp][k0 + kk + tig];
                a[mt][1] = Atf[rb + grp + 8][k0 + kk + tig];
                a[mt][2] = Atf[rb + grp][k0 + kk + tig + 4];
                a[mt][3] = Atf[rb + grp + 8][k0 + kk + tig + 4];
            }
            unsigned b[4][2];
#pragma unroll
            for (int nt = 0; nt < 4; nt++) {
                int cb = warp * 32 + nt * 8;
                b[nt][0] = Wos[cb + grp][kk + tig];
                b[nt][1] = Wos[cb + grp][kk + tig + 4];
            }
#pragma unroll
            for (int mt = 0; mt < 2; mt++)
#pragma unroll
                for (int nt = 0; nt < 4; nt++) {
                    asm volatile(
                        "mma.sync.aligned.m16n8k8.row.col.f32.tf32.tf32.f32 "
                        "{%0,%1,%2,%3}, {%4,%5,%6,%7}, {%8,%9}, {%0,%1,%2,%3};"
                        : "+f"(c[mt][nt][0]), "+f"(c[mt][nt][1]),
                          "+f"(c[mt][nt][2]), "+f"(c[mt][nt][3])
                        : "r"(a[mt][0]), "r"(a[mt][1]), "r"(a[mt][2]), "r"(a[mt][3]),
                          "r"(b[nt][0]), "r"(b[nt][1]));
                }
        }
        __syncthreads();
    }

    // epilogue: rows blk*32 + mt*16 + {grp, grp+8}, cols warp*32 + nt*8 + tig*2
#pragma unroll
    for (int nt = 0; nt < 4; nt++) {
        int gn = warp * 32 + nt * 8 + tig * 2;
        float b0 = bo[gn];
        float b1 = bo[gn + 1];
#pragma unroll
        for (int mt = 0; mt < 2; mt++) {
            int gm = blk * MT + mt * 16 + grp;
            float2 o0 = make_float2(c[mt][nt][0] + b0, c[mt][nt][1] + b1);
            float2 o1 = make_float2(c[mt][nt][2] + b0, c[mt][nt][3] + b1);
            *(float2*)&out[(size_t)gm * CC + gn] = o0;
            *(float2*)&out[(size_t)(gm + 8) * CC + gn] = o1;
        }
    }
}

// ---------------------------------------------------------------------------
extern "C" void kernel_launch(void* const* d_in, const int* in_sizes, int n_in,
                              void* d_out, int out_size)
{
    const float* query  = (const float*)d_in[0];
    const float* refpts = (const float*)d_in[1];
    const float* value  = (const float*)d_in[2];
    const float* Wv     = (const float*)d_in[3];
    const float* bv     = (const float*)d_in[4];
    const float* Woff   = (const float*)d_in[5];
    const float* boff   = (const float*)d_in[6];
    const float* Wa     = (const float*)d_in[7];
    const float* ba     = (const float*)d_in[8];
    const float* Wo     = (const float*)d_in[9];
    const float* bo     = (const float*)d_in[10];
    float* out = (float*)d_out;

    float *p_off, *p_a;
    cudaGetSymbolAddress((void**)&p_off, g_off);
    cudaGetSymbolAddress((void**)&p_a,   g_a);

    static cudaStream_t s1 = nullptr, s2 = nullptr;
    static cudaEvent_t ev_root = nullptr, ev_a = nullptr, ev_pre = nullptr;
    if (!s1) {
        cudaStreamCreateWithFlags(&s1, cudaStreamNonBlocking);
        cudaStreamCreateWithFlags(&s2, cudaStreamNonBlocking);
        cudaEventCreateWithFlags(&ev_root, cudaEventDisableTiming);
        cudaEventCreateWithFlags(&ev_a,    cudaEventDisableTiming);
        cudaEventCreateWithFlags(&ev_pre,  cudaEventDisableTiming);
    }

    const int M = BB * NQ;              // 10752 = 84 * 128
    const int gy = M / GBm;             // 84

    // Fork
    cudaEventRecord(ev_root, 0);
    cudaStreamWaitEvent(s1, ev_root, 0);
    cudaStreamWaitEvent(s2, ev_root, 0);

    // Main stream: v-GEMM starts immediately (border zeroing is disjoint).
    gemm_tf32_kernel<<<dim3(CC / GBn, gy), 256>>>(value, Wv, bv, nullptr, M, CC, CC, 1);

    // Side stream 2: border zero (concurrent with v-GEMM), then a-GEMM.
    zero_border_kernel<<<(BB * NBORDER * 32 + 255) / 256, 256, 0, s2>>>();
    gemm_tf32_kernel<<<dim3((TP + GBn - 1) / GBn, gy), 256, 0, s2>>>(query, Wa, ba, p_a, M, TP, CC, 0);
    cudaEventRecord(ev_a, s2);

    // Side stream 1: off-GEMM, then precompute (needs off + a).
    gemm_tf32_kernel<<<dim3(TP2 / GBn, gy), 256, 0, s1>>>(query, Woff, boff, p_off, M, TP2, CC, 0);
    cudaStreamWaitEvent(s1, ev_a, 0);
    precompute_kernel<<<(NBQH + 255) / 256, 256, 0, s1>>>(refpts);
    cudaEventRecord(ev_pre, s1);

    // Join: fused kernel needs v+border (main/s2 via ev_a chain? border is on
    // s2 before ev_a, precompute waits ev_a, we wait ev_pre) + weights (s1).
    cudaStreamWaitEvent(0, ev_pre, 0);
    fused_sample_out_kernel<<<M / MT, 256>>>(Wo, bo, out);
}

// round 16
// speedup vs baseline: 2.3188x; 2.3188x over previous
#include <cuda_runtime.h>
#include <cuda_fp16.h>
#include <math.h>

// Problem constants
#define BB     2
#define HEADS  8
#define LEVELS 3
#define POINTS 4
#define CC     256
#define HD     32          // CC / HEADS
#define NV     5376        // 64*64 + 32*32 + 16*16
#define NQ     5376
#define TP     96          // HEADS*LEVELS*POINTS
#define TP2    192
#define NBQH   (BB * NQ * HEADS)   // 86016

// Padded value-tensor geometry: each level padded by a 1-cell zero ring.
// L0: 66x66 = 4356, L1: 34x34 = 1156, L2: 18x18 = 324.  Total 5836 cells/batch.
#define PNV    5836
#define P0     0
#define P1     4356
#define P2     5512
#define VP_TOTAL  (BB * PNV * CC)      // 2,988,032 elements

// Scratch (static device allocations — allowed by harness rules)
// g_vph layout is HEAD-MAJOR: ((b*HEADS + h) * PNV + pcell) * HD + hd
// -> adjacent-x corners of one head are contiguous (64B apart), halving
//    the L1tex wavefronts per gather.
__device__ __half  g_vph[VP_TOTAL];
__device__ float   g_off[BB * NQ * TP2];   // sampling offsets
__device__ float   g_a[BB * NQ * TP];      // attention logits
__device__ float   g_tmp[BB * NQ * CC];    // sampled output, layout (b, q, h, hd)
__device__ float4  g_w4[12 * NBQH];        // premult corner weights, [pp][bqh]
__device__ int     g_pidx[12 * NBQH];      // folded element-index of corner(0,0), [pp][bqh]

// ---------------------------------------------------------------------------
// Zero the padded value buffer (fp16: 6MB, ~1.5us). Layout-agnostic.
// ---------------------------------------------------------------------------
__global__ void __launch_bounds__(256) zero_vp_kernel()
{
    int i = blockIdx.x * blockDim.x + threadIdx.x;
    if (i < VP_TOTAL / 8)
        ((uint4*)g_vph)[i] = make_uint4(0u, 0u, 0u, 0u);
}

// ---------------------------------------------------------------------------
// Tensor-core GEMM (tf32 mma.sync) — R9/R11 winner, unchanged math.
// pad_v != 0: epilogue writes fp16 into head-major padded g_vph.
// ---------------------------------------------------------------------------
#define GBm 128
#define GBn 64
#define GBk 32
#define SSTR 36

__device__ __forceinline__ unsigned f2tf32(float f) {
    unsigned u;
    asm("cvt.rna.tf32.f32 %0, %1;" : "=r"(u) : "f"(f));
    return u;
}

// Returns padded cell index within one batch (0..PNV-1) for value row n.
__device__ __forceinline__ int padded_cell(int n) {
    if (n < 4096)      { int y = n >> 6, x = n & 63;                   return P0 + (y + 1) * 66 + (x + 1); }
    else if (n < 5120) { int t = n - 4096; int y = t >> 5, x = t & 31; return P1 + (y + 1) * 34 + (x + 1); }
    else               { int t = n - 5120; int y = t >> 4, x = t & 15; return P2 + (y + 1) * 18 + (x + 1); }
}

__global__ void __launch_bounds__(256, 2) gemm_tf32_kernel(
    const float* __restrict__ A, const float* __restrict__ W,
    const float* __restrict__ bias, float* __restrict__ C,
    int M, int N, int K, int pad_v)
{
    __shared__ unsigned As[GBm][SSTR];
    __shared__ unsigned Ws[GBn][SSTR];

    const int tid  = threadIdx.x;
    const int lane = tid & 31;
    const int warp = tid >> 5;
    const int wm   = warp >> 1;
    const int wn   = warp & 1;
    const int m0   = blockIdx.y * GBm;
    const int n0   = blockIdx.x * GBn;

    const int grp = lane >> 2;
    const int tig = lane & 3;

    int ar[4], ac[4];
    size_t aoff[4];
#pragma unroll
    for (int j = 0; j < 4; j++) {
        int idx = tid + j * 256;
        ar[j] = idx >> 3;
        ac[j] = idx & 7;
        aoff[j] = (size_t)(m0 + ar[j]) * K + ac[j] * 4;
    }
    int wr[2], wc[2], wg[2];
    size_t woff[2];
#pragma unroll
    for (int j = 0; j < 2; j++) {
        int idx = tid + j * 256;
        wr[j] = idx >> 3;
        wc[j] = idx & 7;
        wg[j] = n0 + wr[j];
        woff[j] = (size_t)wg[j] * K + wc[j] * 4;
    }

    float c[2][4][4];
#pragma unroll
    for (int mt = 0; mt < 2; mt++)
#pragma unroll
        for (int nt = 0; nt < 4; nt++)
#pragma unroll
            for (int i = 0; i < 4; i++) c[mt][nt][i] = 0.f;

    float4 pa[4], pw[2];
#pragma unroll
    for (int j = 0; j < 4; j++) pa[j] = *(const float4*)&A[aoff[j]];
#pragma unroll
    for (int j = 0; j < 2; j++)
        pw[j] = (wg[j] < N) ? *(const float4*)&W[woff[j]]
                            : make_float4(0.f, 0.f, 0.f, 0.f);

    for (int k0 = 0; k0 < K; k0 += GBk) {
#pragma unroll
        for (int j = 0; j < 4; j++) {
            uint4 u;
            u.x = f2tf32(pa[j].x); u.y = f2tf32(pa[j].y);
            u.z = f2tf32(pa[j].z); u.w = f2tf32(pa[j].w);
            *(uint4*)&As[ar[j]][ac[j] * 4] = u;
        }
#pragma unroll
        for (int j = 0; j < 2; j++) {
            uint4 u;
            u.x = f2tf32(pw[j].x); u.y = f2tf32(pw[j].y);
            u.z = f2tf32(pw[j].z); u.w = f2tf32(pw[j].w);
            *(uint4*)&Ws[wr[j]][wc[j] * 4] = u;
        }
        __syncthreads();

        const int kn = k0 + GBk;
        if (kn < K) {
#pragma unroll
            for (int j = 0; j < 4; j++) pa[j] = *(const float4*)&A[aoff[j] + kn];
#pragma unroll
            for (int j = 0; j < 2; j++)
                pw[j] = (wg[j] < N) ? *(const float4*)&W[woff[j] + kn]
                                    : make_float4(0.f, 0.f, 0.f, 0.f);
        }

#pragma unroll
        for (int kk = 0; kk < GBk; kk += 8) {
            unsigned a[2][4];
#pragma unroll
            for (int mt = 0; mt < 2; mt++) {
                int rb = wm * 32 + mt * 16;
                a[mt][0] = As[rb + grp][kk + tig];
                a[mt][1] = As[rb + grp + 8][kk + tig];
                a[mt][2] = As[rb + grp][kk + tig + 4];
                a[mt][3] = As[rb + grp + 8][kk + tig + 4];
            }
            unsigned b[4][2];
#pragma unroll
            for (int nt = 0; nt < 4; nt++) {
                int cb = wn * 32 + nt * 8;
                b[nt][0] = Ws[cb + grp][kk + tig];
                b[nt][1] = Ws[cb + grp][kk + tig + 4];
            }
#pragma unroll
            for (int mt = 0; mt < 2; mt++)
#pragma unroll
                for (int nt = 0; nt < 4; nt++) {
                    asm volatile(
                        "mma.sync.aligned.m16n8k8.row.col.f32.tf32.tf32.f32 "
                        "{%0,%1,%2,%3}, {%4,%5,%6,%7}, {%8,%9}, {%0,%1,%2,%3};"
                        : "+f"(c[mt][nt][0]), "+f"(c[mt][nt][1]),
                          "+f"(c[mt][nt][2]), "+f"(c[mt][nt][3])
                        : "r"(a[mt][0]), "r"(a[mt][1]), "r"(a[mt][2]), "r"(a[mt][3]),
                          "r"(b[nt][0]), "r"(b[nt][1]));
                }
        }
        __syncthreads();
    }

    // ---- epilogue ----
    // pad_v: head-major fp16 target. For output element (gm, gn):
    //   b = gm/NV, pcell = padded_cell(gm%NV), h = gn>>5, hd = gn&31
    //   idx = ((b*HEADS + h)*PNV + pcell)*HD + hd
    int pb[2], pc0[2], pc1[2];
#pragma unroll
    for (int mt = 0; mt < 2; mt++) {
        int gm = m0 + wm * 32 + mt * 16 + grp;
        if (pad_v) {
            int b = gm / NV;
            pb[mt]  = b;
            pc0[mt] = padded_cell(gm - b * NV);
            pc1[mt] = padded_cell(gm + 8 - b * NV);   // same batch (same 128-tile)
        } else {
            pb[mt] = 0; pc0[mt] = gm; pc1[mt] = gm + 8;
        }
    }
#pragma unroll
    for (int nt = 0; nt < 4; nt++) {
        int gn = n0 + wn * 32 + nt * 8 + tig * 2;
        if (gn >= N) continue;
        float b0 = bias[gn];
        float b1 = bias[gn + 1];
#pragma unroll
        for (int mt = 0; mt < 2; mt++) {
            float2 o0 = make_float2(c[mt][nt][0] + b0, c[mt][nt][1] + b1);
            float2 o1 = make_float2(c[mt][nt][2] + b0, c[mt][nt][3] + b1);
            if (pad_v) {
                const int h  = gn >> 5;
                const int hd = gn & 31;   // even
                const size_t i0 = ((size_t)(pb[mt] * HEADS + h) * PNV + pc0[mt]) * HD + hd;
                const size_t i1 = ((size_t)(pb[mt] * HEADS + h) * PNV + pc1[mt]) * HD + hd;
                *(__half2*)&g_vph[i0] = __floats2half2_rn(o0.x, o0.y);
                *(__half2*)&g_vph[i1] = __floats2half2_rn(o1.x, o1.y);
            } else {
                *(float2*)&C[(size_t)pc0[mt] * N + gn] = o0;
                *(float2*)&C[(size_t)pc1[mt] * N + gn] = o1;
            }
        }
    }
}

// ---------------------------------------------------------------------------
// Precompute: softmax + sampling coordinates/weights, once per (b,q,h).
// idx00 now head-major: ((b*HEADS + h)*PNV + cell00) * HD
// ---------------------------------------------------------------------------
__global__ void __launch_bounds__(256) precompute_kernel(
    const float* __restrict__ refpts)
{
    const int t = blockIdx.x * blockDim.x + threadIdx.x;
    if (t >= NBQH) return;
    const int h  = t % HEADS;
    const int bq = t / HEADS;
    const int b  = bq / NQ;

    const float rx = refpts[bq * 2 + 0];
    const float ry = refpts[bq * 2 + 1];

    const float* __restrict__ off   = g_off + bq * TP2 + h * (LEVELS * POINTS * 2);
    const float* __restrict__ logit = g_a   + bq * TP  + h * (LEVELS * POINTS);

    float e[12];
    float mx = -INFINITY;
#pragma unroll
    for (int i = 0; i < 12; i++) { e[i] = logit[i]; mx = fmaxf(mx, e[i]); }
    float s = 0.f;
#pragma unroll
    for (int i = 0; i < 12; i++) { e[i] = __expf(e[i] - mx); s += e[i]; }
    const float inv = 1.f / s;

    const int plvl_start[LEVELS] = {P0, P1, P2};
    const int lvl_dim[LEVELS]    = {64, 32, 16};

    const int hbase = (b * HEADS + h) * PNV;

#pragma unroll
    for (int lvl = 0; lvl < LEVELS; lvl++) {
        const int Wd = lvl_dim[lvl];
        const int Pw = Wd + 2;
        const float fW = (float)Wd;
#pragma unroll
        for (int p = 0; p < POINTS; p++) {
            const int pp = lvl * POINTS + p;
            float lx = rx + off[pp * 2 + 0];
            float ly = ry + off[pp * 2 + 1];
            lx = fminf(fmaxf(lx, 0.f), 1.f);
            ly = fminf(fmaxf(ly, 0.f), 1.f);
            const float aw = e[pp] * inv;

            const float x = lx * fW - 0.5f;
            const float y = ly * fW - 0.5f;   // Hd == Wd
            const float x0f = floorf(x);
            const float y0f = floorf(y);
            const int x0 = (int)x0f;
            const int y0 = (int)y0f;
            const float wx1 = x - x0f;
            const float wy1 = y - y0f;
            const float wx0 = 1.f - wx1;
            const float wy0 = 1.f - wy1;

            float4 w4;
            w4.x = aw * wx0 * wy0;   // corner (dy=0,dx=0)
            w4.y = aw * wx1 * wy0;   // corner (dy=0,dx=1)
            w4.z = aw * wx0 * wy1;   // corner (dy=1,dx=0)
            w4.w = aw * wx1 * wy1;   // corner (dy=1,dx=1)

            const int cell00 = plvl_start[lvl] + (y0 + 1) * Pw + (x0 + 1);
            const int idx00  = (hbase + cell00) * HD;

            g_w4 [pp * NBQH + t] = w4;
            g_pidx[pp * NBQH + t] = idx00;
        }
    }
}

// ---------------------------------------------------------------------------
// Bilinear sampling over head-major fp16 v. One warp per (b,q,h);
// lane = pt*16 + cg*4 + q; two points per iteration.
// Corner offset = (dy*Pw + dx)*HD — adjacent-x corners contiguous (64B), so
// each corner-pair gather coalesces into one 128B segment.
// fp32 accumulation; reduction over pt+cg via shfl_xor(4,8,16).
// ---------------------------------------------------------------------------
__global__ void __launch_bounds__(256) sample_kernel()
{
    const int warp = (blockIdx.x * blockDim.x + threadIdx.x) >> 5;
    const int lane = threadIdx.x & 31;
    if (warp >= NBQH) return;

    const int pt = (lane >> 4) & 1;   // point within pair
    const int cg = (lane >> 2) & 3;   // corner
    const int q  = lane & 3;          // chunk: channels q*8 .. q*8+7
    const int dx = cg & 1;
    const int dy = cg >> 1;

    // Per-lane corner offsets by level (element units; Pw = 66/34/18)
    const int coff0 = (dy * 66 + dx) * HD + q * 8;
    const int coff1 = (dy * 34 + dx) * HD + q * 8;
    const int coff2 = (dy * 18 + dx) * HD + q * 8;

    float acc[8];
#pragma unroll
    for (int j = 0; j < 8; j++) acc[j] = 0.f;

#pragma unroll
    for (int i = 0; i < 6; i++) {          // point pairs: pp = 2i + pt
        const int pp = 2 * i + pt;
        const float4 w4  = g_w4 [pp * NBQH + warp];
        const int  idx00 = g_pidx[pp * NBQH + warp];

        const float w = (cg == 0) ? w4.x : (cg == 1) ? w4.y
                      : (cg == 2) ? w4.z : w4.w;

        const int coff = (i < 2) ? coff0 : (i < 4) ? coff1 : coff2;
        const uint4 raw = *(const uint4*)&g_vph[idx00 + coff];

        const __half2* h2 = (const __half2*)&raw;
#pragma unroll
        for (int j = 0; j < 4; j++) {
            const float2 f = __half22float2(h2[j]);
            acc[2 * j + 0] = fmaf(w, f.x, acc[2 * j + 0]);
            acc[2 * j + 1] = fmaf(w, f.y, acc[2 * j + 1]);
        }
    }

    // Reduce over pt (bit 4) and cg (bits 2-3); lanes 0..3 keep chunk q.
#pragma unroll
    for (int ofs = 4; ofs <= 16; ofs <<= 1) {
#pragma unroll
        for (int j = 0; j < 8; j++)
            acc[j] += __shfl_xor_sync(0xffffffffu, acc[j], ofs);
    }

    if (lane < 4) {
        float* dst = &g_tmp[warp * HD + q * 8];
        *(float4*)&dst[0] = make_float4(acc[0], acc[1], acc[2], acc[3]);
        *(float4*)&dst[4] = make_float4(acc[4], acc[5], acc[6], acc[7]);
    }
}

// ---------------------------------------------------------------------------
extern "C" void kernel_launch(void* const* d_in, const int* in_sizes, int n_in,
                              void* d_out, int out_size)
{
    const float* query  = (const float*)d_in[0];
    const float* refpts = (const float*)d_in[1];
    const float* value  = (const float*)d_in[2];
    const float* Wv     = (const float*)d_in[3];
    const float* bv     = (const float*)d_in[4];
    const float* Woff   = (const float*)d_in[5];
    const float* boff   = (const float*)d_in[6];
    const float* Wa     = (const float*)d_in[7];
    const float* ba     = (const float*)d_in[8];
    const float* Wo     = (const float*)d_in[9];
    const float* bo     = (const float*)d_in[10];
    float* out = (float*)d_out;

    float *p_off, *p_a, *p_tmp;
    cudaGetSymbolAddress((void**)&p_off, g_off);
    cudaGetSymbolAddress((void**)&p_a,   g_a);
    cudaGetSymbolAddress((void**)&p_tmp, g_tmp);

    static cudaStream_t s1 = nullptr, s2 = nullptr;
    static cudaEvent_t ev_root = nullptr, ev_a = nullptr, ev_pre = nullptr;
    if (!s1) {
        cudaStreamCreateWithFlags(&s1, cudaStreamNonBlocking);
        cudaStreamCreateWithFlags(&s2, cudaStreamNonBlocking);
        cudaEventCreateWithFlags(&ev_root, cudaEventDisableTiming);
        cudaEventCreateWithFlags(&ev_a,    cudaEventDisableTiming);
        cudaEventCreateWithFlags(&ev_pre,  cudaEventDisableTiming);
    }

    const int M = BB * NQ;              // 10752 = 84 * 128
    const int gy = M / GBm;             // 84

    // Fork
    cudaEventRecord(ev_root, 0);
    cudaStreamWaitEvent(s1, ev_root, 0);
    cudaStreamWaitEvent(s2, ev_root, 0);

    // Main stream: zero padded v buffer, then v-GEMM into it (fp16 epilogue).
    zero_vp_kernel<<<(VP_TOTAL / 8 + 255) / 256, 256>>>();
    gemm_tf32_kernel<<<dim3(CC / GBn, gy), 256>>>(value, Wv, bv, nullptr, M, CC, CC, 1);

    // Side stream 2: a = query @ Wa^T + ba
    gemm_tf32_kernel<<<dim3((TP + GBn - 1) / GBn, gy), 256, 0, s2>>>(query, Wa, ba, p_a, M, TP, CC, 0);
    cudaEventRecord(ev_a, s2);

    // Side stream 1: off = query @ Woff^T + boff, then precompute (needs off + a)
    gemm_tf32_kernel<<<dim3(TP2 / GBn, gy), 256, 0, s1>>>(query, Woff, boff, p_off, M, TP2, CC, 0);
    cudaStreamWaitEvent(s1, ev_a, 0);
    precompute_kernel<<<(NBQH + 255) / 256, 256, 0, s1>>>(refpts);
    cudaEventRecord(ev_pre, s1);

    // Join: sampler needs v (main) + precomputed weights/indices (s1).
    cudaStreamWaitEvent(0, ev_pre, 0);
    sample_kernel<<<NBQH / 8, 256>>>();

    // out = tmp @ Wo^T + bo
    gemm_tf32_kernel<<<dim3(CC / GBn, gy), 256>>>(p_tmp, Wo, bo, out, M, CC, CC, 0);
}